// round 16
// baseline (speedup 1.0000x reference)
#include <cuda_runtime.h>
#include <cstdint>

// ============================================================================
// QuantizedLinear: out_f32 = clip(round(fma((x_q-128)@W^T, 2e-4, bias)),0..255)
// M=4096, K=4096, N=11008.
// ROUND 16: (a) fuse prepass into ONE kernel (2 launches/call -> ncu finally
// captures the GEMM), (b) replace per-iter __syncthreads with per-slot EMPTY
// mbarriers so warps desynchronize (cover long fallback-MMA latency),
// (c) 2 CTAs/SM pinned, m-fastest grid for L2-resident A.
// ============================================================================

#define MDIM 4096
#define KDIM 4096
#define NDIM 11008

#define X_ZP 128
#define SXW_SCALE (0.02f * 0.01f)

#define BM 128
#define BN 128
#define BK 64
#define NST 3
#define KTILES (KDIM / BK)               // 64

#define A_STAGE_BYTES (BM * BK)          // 8192
#define B_STAGE_BYTES (BN * BK)          // 8192
#define STAGE_BYTES (A_STAGE_BYTES + B_STAGE_BYTES)   // 16384
#define SMEM_TOTAL (NST * STAGE_BYTES)   // 49152

// K-tiled, pre-swizzled int8 scratch: [kt][row][64B chunk-swizzled]
__device__ __align__(256) int8_t g_qk_At[(size_t)MDIM * KDIM];
__device__ __align__(256) int8_t g_qk_Bt[(size_t)NDIM * KDIM];

// ---------------------------------------------------------------- PTX helpers
__device__ __forceinline__ uint32_t qk_smem_u32(const void* p) {
    uint32_t a;
    asm("{ .reg .u64 t; cvta.to.shared.u64 t, %1; cvt.u32.u64 %0, t; }"
        : "=r"(a) : "l"(p));
    return a;
}
__device__ __forceinline__ void qk_mbar_init(uint32_t mb, uint32_t cnt) {
    asm volatile("mbarrier.init.shared.b64 [%0], %1;" :: "r"(mb), "r"(cnt) : "memory");
}
__device__ __forceinline__ void qk_mbar_arrive(uint32_t mb) {
    asm volatile("mbarrier.arrive.shared.b64 _, [%0];" :: "r"(mb) : "memory");
}
__device__ __forceinline__ void qk_mbar_expect_tx(uint32_t mb, uint32_t bytes) {
    asm volatile("mbarrier.arrive.expect_tx.shared.b64 _, [%0], %1;"
                 :: "r"(mb), "r"(bytes) : "memory");
}
__device__ __forceinline__ void qk_mbar_wait(uint32_t mb, uint32_t phase) {
    asm volatile(
        "{\n\t.reg .pred P;\n\t"
        "QKW_%=:\n\t"
        "mbarrier.try_wait.parity.acquire.cta.shared::cta.b64 P, [%0], %1, 0x989680;\n\t"
        "@!P bra QKW_%=;\n\t}"
        :: "r"(mb), "r"(phase) : "memory");
}
__device__ __forceinline__ void qk_bulk_g2s(uint32_t dst, const void* src,
                                            uint32_t bytes, uint32_t mb) {
    asm volatile(
        "cp.async.bulk.shared::cluster.global.mbarrier::complete_tx::bytes "
        "[%0], [%1], %2, [%3];"
        :: "r"(dst), "l"(src), "r"(bytes), "r"(mb) : "memory");
}
__device__ __forceinline__ void qk_ldsm_x4(uint32_t& r0, uint32_t& r1,
                                           uint32_t& r2, uint32_t& r3,
                                           uint32_t addr) {
    asm volatile("ldmatrix.sync.aligned.m8n8.x4.shared.b16 {%0,%1,%2,%3}, [%4];"
                 : "=r"(r0), "=r"(r1), "=r"(r2), "=r"(r3) : "r"(addr));
}
__device__ __forceinline__ void qk_mma_s8(int* c, const uint32_t* a,
                                          uint32_t b0, uint32_t b1) {
    asm volatile(
        "mma.sync.aligned.m16n8k32.row.col.s32.s8.s8.s32 "
        "{%0,%1,%2,%3}, {%4,%5,%6,%7}, {%8,%9}, {%0,%1,%2,%3};"
        : "+r"(c[0]), "+r"(c[1]), "+r"(c[2]), "+r"(c[3])
        : "r"(a[0]), "r"(a[1]), "r"(a[2]), "r"(a[3]), "r"(b0), "r"(b1));
}
__device__ __forceinline__ uint32_t qk_sw(int row, int c16) {
    return (uint32_t)(row * 64 + ((c16 ^ ((row >> 1) & 3)) << 4));
}

// ------------------------------------------------------------- fused prepass
__global__ void qk_cvt(const int* __restrict__ xq, const int* __restrict__ wq,
                       int nca, int ncb) {
    int i = blockIdx.x * blockDim.x + threadIdx.x;
    if (i < nca) {                        // ---- A chunk ----
        const int c16 = i & 3;
        const int rowg = i >> 2;          // kt*MDIM + m
        const int m = rowg & (MDIM - 1);
        const int kt = rowg >> 12;
        const int* src = xq + (size_t)m * KDIM + kt * 64 + c16 * 16;
        uint32_t pk[4];
#pragma unroll
        for (int j = 0; j < 4; j++) {
            const int4 v = *(const int4*)(src + 4 * j);
            pk[j] =  ((uint32_t)(uint8_t)(v.x - X_ZP))
                  | (((uint32_t)(uint8_t)(v.y - X_ZP)) << 8)
                  | (((uint32_t)(uint8_t)(v.z - X_ZP)) << 16)
                  | (((uint32_t)(uint8_t)(v.w - X_ZP)) << 24);
        }
        const int s = c16 ^ ((m >> 1) & 3);
        *(uint4*)(g_qk_At + (size_t)rowg * 64 + s * 16) =
            make_uint4(pk[0], pk[1], pk[2], pk[3]);
    } else if (i < nca + ncb) {           // ---- B chunk ----
        const int j0 = i - nca;
        const int c16 = j0 & 3;
        const int rowg = j0 >> 2;         // kt*NDIM + n
        const int kt = rowg / NDIM;
        const int n = rowg - kt * NDIM;
        const int* src = wq + (size_t)n * KDIM + kt * 64 + c16 * 16;
        uint32_t pk[4];
#pragma unroll
        for (int j = 0; j < 4; j++) {
            const int4 v = *(const int4*)(src + 4 * j);
            pk[j] =  ((uint32_t)(uint8_t)v.x)
                  | (((uint32_t)(uint8_t)v.y) << 8)
                  | (((uint32_t)(uint8_t)v.z) << 16)
                  | (((uint32_t)(uint8_t)v.w) << 24);
        }
        const int s = c16 ^ ((n >> 1) & 3);
        *(uint4*)(g_qk_Bt + (size_t)rowg * 64 + s * 16) =
            make_uint4(pk[0], pk[1], pk[2], pk[3]);
    }
}

// ---------------------------------------------------------------- GEMM kernel
__global__ void __launch_bounds__(256, 2) qk_gemm(
    float* __restrict__ out, const float* __restrict__ bias)
{
    __shared__ __align__(128) int8_t smem[SMEM_TOTAL];
    __shared__ __align__(8) uint64_t mfull[NST];
    __shared__ __align__(8) uint64_t mempty[NST];

    const uint32_t sb = qk_smem_u32(smem);
    const uint32_t mf0 = qk_smem_u32(mfull);
    const uint32_t me0 = qk_smem_u32(mempty);
    const int tid = threadIdx.x;
    const int wid = tid >> 5;
    const int lid = tid & 31;
    const int wm = wid >> 2;          // 0..1 : 64-row M chunk
    const int wn = wid & 3;           // 0..3 : 32-col N chunk

    const int m0 = blockIdx.x * BM;   // m fastest: A (16MB) L2-resident,
    const int n0 = blockIdx.y * BN;   //            B streamed ~once

    if (tid == 0)
        for (int s = 0; s < NST; s++) {
            qk_mbar_init(mf0 + 8 * s, 1);      // tx-completed by bulk copies
            qk_mbar_init(me0 + 8 * s, 8);      // one arrive per warp
        }
    __syncthreads();

    auto issue = [&](int kt) {
        const int s = kt % NST;
        const uint32_t mb = mf0 + 8 * s;
        qk_mbar_expect_tx(mb, STAGE_BYTES);
        qk_bulk_g2s(sb + s * STAGE_BYTES,
                    g_qk_At + ((size_t)kt * MDIM + m0) * 64, A_STAGE_BYTES, mb);
        qk_bulk_g2s(sb + s * STAGE_BYTES + A_STAGE_BYTES,
                    g_qk_Bt + ((size_t)kt * NDIM + n0) * 64, B_STAGE_BYTES, mb);
    };

    int acc[4][4][4];
#pragma unroll
    for (int i = 0; i < 4; i++)
#pragma unroll
        for (int j = 0; j < 4; j++)
#pragma unroll
            for (int e = 0; e < 4; e++) acc[i][j][e] = 0;

    if (tid == 0) { issue(0); issue(1); issue(2); }   // prefill all stages

    const int lrow = lid & 15;
    const int lc   = lid >> 4;

    for (int kt = 0; kt < KTILES; kt++) {
        const int sc = kt % NST;
        const uint32_t ph = (uint32_t)(kt / NST) & 1u;

        qk_mbar_wait(mf0 + 8 * sc, ph);       // copy for this tile landed

        const uint32_t sA = sb + sc * STAGE_BYTES;
        const uint32_t sBB = sA + A_STAGE_BYTES;

#pragma unroll
        for (int kk = 0; kk < 2; kk++) {
            const int c16 = kk * 2 + lc;
            uint32_t a[4][4];
#pragma unroll
            for (int mf = 0; mf < 4; mf++) {
                const int row = wm * 64 + mf * 16 + lrow;
                qk_ldsm_x4(a[mf][0], a[mf][1], a[mf][2], a[mf][3],
                           sA + qk_sw(row, c16));
            }
            uint32_t bq[2][4];
#pragma unroll
            for (int bh = 0; bh < 2; bh++) {
                const int row = wn * 32 + bh * 16 + lrow;
                qk_ldsm_x4(bq[bh][0], bq[bh][1], bq[bh][2], bq[bh][3],
                           sBB + qk_sw(row, c16));
            }
#pragma unroll
            for (int mf = 0; mf < 4; mf++)
#pragma unroll
                for (int nf = 0; nf < 4; nf++) {
                    const int bh = nf >> 1, pr = nf & 1;
                    qk_mma_s8(acc[mf][nf], a[mf], bq[bh][pr], bq[bh][pr + 2]);
                }
        }

        // this warp is done reading slot sc for this round
        if (lid == 0) qk_mbar_arrive(me0 + 8 * sc);

        // producer refills the slot once ALL warps have released it;
        // other warps do NOT block here -> they drift ahead (latency cover)
        if (tid == 0 && kt + NST < KTILES) {
            qk_mbar_wait(me0 + 8 * sc, ph);   // empties round kt/NST complete
            issue(kt + NST);
        }
    }

    // -------- epilogue: dequant + bias + requant; FLOAT32 output --------
    const float sxw = SXW_SCALE;
    const int qrow = lid >> 2;
    const int qcol = (lid & 3) * 2;

#pragma unroll
    for (int nf = 0; nf < 4; nf++) {
        const int col = n0 + wn * 32 + nf * 8 + qcol;
        const float b0 = bias[col];
        const float b1 = bias[col + 1];
#pragma unroll
        for (int mf = 0; mf < 4; mf++) {
            const int r0 = m0 + wm * 64 + mf * 16 + qrow;
#pragma unroll
            for (int h = 0; h < 2; h++) {
                const long row = r0 + h * 8;
                float y0 = __fmaf_rn((float)acc[mf][nf][2 * h + 0], sxw, b0);
                float y1 = __fmaf_rn((float)acc[mf][nf][2 * h + 1], sxw, b1);
                float q0 = fminf(fmaxf(rintf(y0), 0.0f), 255.0f);
                float q1 = fminf(fmaxf(rintf(y1), 0.0f), 255.0f);
                float2 v = make_float2(q0, q1);
                *(float2*)(out + row * (long)NDIM + col) = v;
            }
        }
    }
}

// --------------------------------------------------------------------- launch
extern "C" void kernel_launch(void* const* d_in, const int* in_sizes, int n_in,
                              void* d_out, int out_size) {
    (void)in_sizes; (void)n_in; (void)out_size;

    const int*   xq   = (const int*)d_in[0];
    const int*   wq   = (const int*)d_in[1];
    const float* bias = (const float*)d_in[2];

    const int nca = (MDIM * KDIM) / 16;   // 1,048,576
    const int ncb = (NDIM * KDIM) / 16;   // 2,818,048
    const int nct = nca + ncb;            // 3,866,624
    qk_cvt<<<(nct + 255) / 256, 256>>>(xq, wq, nca, ncb);

    dim3 grid(MDIM / BM, NDIM / BN);      // (32, 86) m fastest
    qk_gemm<<<grid, 256>>>((float*)d_out, bias);
}

// round 17
// speedup vs baseline: 1.2864x; 1.2864x over previous
#include <cuda_runtime.h>
#include <cstdint>

// ============================================================================
// QuantizedLinear: out_f32 = clip(round(fma((x_q-128)@W^T, 2e-4, bias)),0..255)
// M=4096, K=4096, N=11008.
// ROUND 17: HYBRID dual-pipe GEMM. tensor pipe is saturated (94%) at the
// legacy-IMMA fallback rate while fma/alu sit idle -> run BOTH engines:
//   warps 0-7 : IMMA m16n8k32 on cols [n0, n0+128)      (tensor pipe)
//   warps 8-15: dp4a            on cols [n0+128, n0+256) (alu pipe)
// sharing the A smem stage. 128x256 tile, 3-stage bulk-copy ring.
// ============================================================================

#define MDIM 4096
#define KDIM 4096
#define NDIM 11008

#define X_ZP 128
#define SXW_SCALE (0.02f * 0.01f)

#define BM 128
#define BNI 128                          // IMMA columns
#define BND 128                          // dp4a columns
#define BN (BNI + BND)                   // 256
#define BK 64
#define NST 3
#define KTILES (KDIM / BK)               // 64
#define NGRP (NDIM / BN)                 // 43

#define A_BYTES  (BM * BK)               // 8192
#define BI_BYTES (BNI * BK)              // 8192
#define BD_BYTES (BND * BK)              // 8192
#define STAGE_BYTES (A_BYTES + BI_BYTES + BD_BYTES)   // 24576
#define SMEM_TOTAL (NST * STAGE_BYTES)   // 73728 (dynamic)

// scratch: A (imma-swizzled, shared by both engines), B split per engine
__device__ __align__(256) int8_t g_At[(size_t)KTILES * MDIM * 64];        // 16MB
__device__ __align__(256) int8_t g_Bi[(size_t)KTILES * NGRP * BI_BYTES];  // 22.5MB
__device__ __align__(256) int8_t g_Bd[(size_t)KTILES * NGRP * BD_BYTES];  // 22.5MB

// ---------------------------------------------------------------- PTX helpers
__device__ __forceinline__ uint32_t qk_smem_u32(const void* p) {
    uint32_t a;
    asm("{ .reg .u64 t; cvta.to.shared.u64 t, %1; cvt.u32.u64 %0, t; }"
        : "=r"(a) : "l"(p));
    return a;
}
__device__ __forceinline__ void qk_mbar_init(uint32_t mb, uint32_t cnt) {
    asm volatile("mbarrier.init.shared.b64 [%0], %1;" :: "r"(mb), "r"(cnt) : "memory");
}
__device__ __forceinline__ void qk_mbar_expect_tx(uint32_t mb, uint32_t bytes) {
    asm volatile("mbarrier.arrive.expect_tx.shared.b64 _, [%0], %1;"
                 :: "r"(mb), "r"(bytes) : "memory");
}
__device__ __forceinline__ void qk_mbar_wait(uint32_t mb, uint32_t phase) {
    asm volatile(
        "{\n\t.reg .pred P;\n\t"
        "QKW_%=:\n\t"
        "mbarrier.try_wait.parity.acquire.cta.shared::cta.b64 P, [%0], %1, 0x989680;\n\t"
        "@!P bra QKW_%=;\n\t}"
        :: "r"(mb), "r"(phase) : "memory");
}
__device__ __forceinline__ void qk_bulk_g2s(uint32_t dst, const void* src,
                                            uint32_t bytes, uint32_t mb) {
    asm volatile(
        "cp.async.bulk.shared::cluster.global.mbarrier::complete_tx::bytes "
        "[%0], [%1], %2, [%3];"
        :: "r"(dst), "l"(src), "r"(bytes), "r"(mb) : "memory");
}
__device__ __forceinline__ void qk_ldsm_x4(uint32_t& r0, uint32_t& r1,
                                           uint32_t& r2, uint32_t& r3,
                                           uint32_t addr) {
    asm volatile("ldmatrix.sync.aligned.m8n8.x4.shared.b16 {%0,%1,%2,%3}, [%4];"
                 : "=r"(r0), "=r"(r1), "=r"(r2), "=r"(r3) : "r"(addr));
}
__device__ __forceinline__ void qk_mma_s8(int* c, const uint32_t* a,
                                          uint32_t b0, uint32_t b1) {
    asm volatile(
        "mma.sync.aligned.m16n8k32.row.col.s32.s8.s8.s32 "
        "{%0,%1,%2,%3}, {%4,%5,%6,%7}, {%8,%9}, {%0,%1,%2,%3};"
        : "+r"(c[0]), "+r"(c[1]), "+r"(c[2]), "+r"(c[3])
        : "r"(a[0]), "r"(a[1]), "r"(a[2]), "r"(a[3]), "r"(b0), "r"(b1));
}
__device__ __forceinline__ uint32_t qk_sw(int row, int c16) {
    return (uint32_t)(row * 64 + ((c16 ^ ((row >> 1) & 3)) << 4));
}

// ------------------------------------------------------------- fused prepass
__global__ void qk_cvt(const int* __restrict__ xq, const int* __restrict__ wq,
                       int nca, int ncb) {
    int i = blockIdx.x * blockDim.x + threadIdx.x;
    if (i < nca) {                        // ---- A chunk (imma-swizzled) ----
        const int c16 = i & 3;
        const int rowg = i >> 2;          // kt*MDIM + m
        const int m = rowg & (MDIM - 1);
        const int kt = rowg >> 12;
        const int* src = xq + (size_t)m * KDIM + kt * 64 + c16 * 16;
        uint32_t pk[4];
#pragma unroll
        for (int j = 0; j < 4; j++) {
            const int4 v = *(const int4*)(src + 4 * j);
            pk[j] =  ((uint32_t)(uint8_t)(v.x - X_ZP))
                  | (((uint32_t)(uint8_t)(v.y - X_ZP)) << 8)
                  | (((uint32_t)(uint8_t)(v.z - X_ZP)) << 16)
                  | (((uint32_t)(uint8_t)(v.w - X_ZP)) << 24);
        }
        const int s = c16 ^ ((m >> 1) & 3);
        *(uint4*)(g_At + (size_t)rowg * 64 + s * 16) =
            make_uint4(pk[0], pk[1], pk[2], pk[3]);
    } else if (i < nca + ncb) {           // ---- B chunk (route by half) ----
        const int j0 = i - nca;
        const int c16 = j0 & 3;
        const int rowg = j0 >> 2;         // kt*NDIM + n
        const int kt = rowg / NDIM;
        const int n = rowg - kt * NDIM;
        const int* src = wq + (size_t)n * KDIM + kt * 64 + c16 * 16;
        uint32_t pk[4];
#pragma unroll
        for (int j = 0; j < 4; j++) {
            const int4 v = *(const int4*)(src + 4 * j);
            pk[j] =  ((uint32_t)(uint8_t)v.x)
                  | (((uint32_t)(uint8_t)v.y) << 8)
                  | (((uint32_t)(uint8_t)v.z) << 16)
                  | (((uint32_t)(uint8_t)v.w) << 24);
        }
        const int gi = n >> 8;            // 256-col group
        const int nl = n & 127;           // row within half
        const size_t base = ((size_t)kt * NGRP + gi) * 8192;
        if (((n >> 7) & 1) == 0) {        // imma half: row-major-64B swizzled
            const int s = c16 ^ ((nl >> 1) & 3);
            *(uint4*)(g_Bi + base + nl * 64 + s * 16) =
                make_uint4(pk[0], pk[1], pk[2], pk[3]);
        } else {                          // dp4a half: [kc][n] u32
            uint32_t* d = (uint32_t*)(g_Bd + base);
#pragma unroll
            for (int j = 0; j < 4; j++)
                d[(c16 * 4 + j) * BND + nl] = pk[j];
        }
    }
}

// ---------------------------------------------------------------- GEMM kernel
__global__ void __launch_bounds__(512, 1) qk_gemm(
    float* __restrict__ out, const float* __restrict__ bias)
{
    extern __shared__ __align__(128) int8_t smem[];
    __shared__ __align__(8) uint64_t mfull[NST];

    const uint32_t sb = qk_smem_u32(smem);
    const uint32_t mf0 = qk_smem_u32(mfull);
    const int tid = threadIdx.x;
    const int wid = tid >> 5;
    const int lid = tid & 31;

    const int m0 = blockIdx.x * BM;       // m fastest: A (16MB s8) L2-resident
    const int n0 = blockIdx.y * BN;
    const int gi = blockIdx.y;

    if (tid == 0)
        for (int s = 0; s < NST; s++) qk_mbar_init(mf0 + 8 * s, 1);
    __syncthreads();

    auto issue = [&](int kt) {
        const int s = kt % NST;
        const uint32_t mb = mf0 + 8 * s;
        const size_t bbase = ((size_t)kt * NGRP + gi) * 8192;
        qk_mbar_expect_tx(mb, STAGE_BYTES);
        qk_bulk_g2s(sb + s * STAGE_BYTES,
                    g_At + ((size_t)kt * MDIM + m0) * 64, A_BYTES, mb);
        qk_bulk_g2s(sb + s * STAGE_BYTES + A_BYTES, g_Bi + bbase, BI_BYTES, mb);
        qk_bulk_g2s(sb + s * STAGE_BYTES + A_BYTES + BI_BYTES,
                    g_Bd + bbase, BD_BYTES, mb);
    };

    // -------- per-engine state --------
    int acc[4][4][4];                     // IMMA accumulators (warps 0-7)
    int accd[8][8];                       // dp4a accumulators (warps 8-15)
    if (wid < 8) {
#pragma unroll
        for (int i = 0; i < 4; i++)
#pragma unroll
            for (int j = 0; j < 4; j++)
#pragma unroll
                for (int e = 0; e < 4; e++) acc[i][j][e] = 0;
    } else {
#pragma unroll
        for (int i = 0; i < 8; i++)
#pragma unroll
            for (int j = 0; j < 8; j++) accd[i][j] = 0;
    }

    if (tid == 0) { issue(0); issue(1); }

    const int wm = wid >> 2;              // imma: 64-row chunk
    const int wn = wid & 3;               // imma: 32-col chunk
    const int lrow = lid & 15;
    const int lc   = lid >> 4;
    const int t  = tid - 256;             // dp: 0..255
    const int tx = t & 15;                // dp: 8-col group
    const int ty = t >> 4;                // dp: 8-row group

    for (int kt = 0; kt < KTILES; kt++) {
        const int sc = kt % NST;
        const uint32_t ph = (uint32_t)(kt / NST) & 1u;

        if (tid == 0 && kt + 2 < KTILES) issue(kt + 2);
        qk_mbar_wait(mf0 + 8 * sc, ph);

        const uint32_t sA  = sb + sc * STAGE_BYTES;
        const uint32_t sBi = sA + A_BYTES;
        const uint32_t sBd = sBi + BI_BYTES;

        if (wid < 8) {
            // ---------------- IMMA engine (tensor pipe) ----------------
#pragma unroll
            for (int kk = 0; kk < 2; kk++) {
                const int c16 = kk * 2 + lc;
                uint32_t a[4][4];
#pragma unroll
                for (int mf = 0; mf < 4; mf++) {
                    const int row = wm * 64 + mf * 16 + lrow;
                    qk_ldsm_x4(a[mf][0], a[mf][1], a[mf][2], a[mf][3],
                               sA + qk_sw(row, c16));
                }
                uint32_t bq[2][4];
#pragma unroll
                for (int bh = 0; bh < 2; bh++) {
                    const int row = wn * 32 + bh * 16 + lrow;
                    qk_ldsm_x4(bq[bh][0], bq[bh][1], bq[bh][2], bq[bh][3],
                               sBi + qk_sw(row, c16));
                }
#pragma unroll
                for (int mf = 0; mf < 4; mf++)
#pragma unroll
                    for (int nf = 0; nf < 4; nf++) {
                        const int bh = nf >> 1, pr = nf & 1;
                        qk_mma_s8(acc[mf][nf], a[mf], bq[bh][pr], bq[bh][pr + 2]);
                    }
            }
        } else {
            // ---------------- dp4a engine (alu pipe) ----------------
#pragma unroll 4
            for (int kc = 0; kc < 16; kc++) {
                uint32_t av[8];
#pragma unroll
                for (int i = 0; i < 8; i++) {
                    const int row = ty * 8 + i;
                    const uint32_t addr = sA + row * 64
                        + ((((kc >> 2) ^ ((row >> 1) & 3)) << 4) | ((kc & 3) << 2));
                    asm volatile("ld.shared.b32 %0, [%1];" : "=r"(av[i]) : "r"(addr));
                }
                uint32_t bv[8];
                asm volatile("ld.shared.v4.b32 {%0,%1,%2,%3}, [%4];"
                             : "=r"(bv[0]), "=r"(bv[1]), "=r"(bv[2]), "=r"(bv[3])
                             : "r"(sBd + kc * (BND * 4) + tx * 32));
                asm volatile("ld.shared.v4.b32 {%0,%1,%2,%3}, [%4];"
                             : "=r"(bv[4]), "=r"(bv[5]), "=r"(bv[6]), "=r"(bv[7])
                             : "r"(sBd + kc * (BND * 4) + tx * 32 + 16));
#pragma unroll
                for (int i = 0; i < 8; i++)
#pragma unroll
                    for (int j = 0; j < 8; j++)
                        accd[i][j] = __dp4a((int)av[i], (int)bv[j], accd[i][j]);
            }
        }
        __syncthreads();
    }

    // -------- epilogue: dequant + bias + requant; FLOAT32 output --------
    const float sxw = SXW_SCALE;
    if (wid < 8) {
        const int qrow = lid >> 2;
        const int qcol = (lid & 3) * 2;
#pragma unroll
        for (int nf = 0; nf < 4; nf++) {
            const int col = n0 + wn * 32 + nf * 8 + qcol;
            const float b0 = bias[col];
            const float b1 = bias[col + 1];
#pragma unroll
            for (int mf = 0; mf < 4; mf++) {
                const int r0 = m0 + wm * 64 + mf * 16 + qrow;
#pragma unroll
                for (int h = 0; h < 2; h++) {
                    const long row = r0 + h * 8;
                    float y0 = __fmaf_rn((float)acc[mf][nf][2 * h + 0], sxw, b0);
                    float y1 = __fmaf_rn((float)acc[mf][nf][2 * h + 1], sxw, b1);
                    float q0 = fminf(fmaxf(rintf(y0), 0.0f), 255.0f);
                    float q1 = fminf(fmaxf(rintf(y1), 0.0f), 255.0f);
                    *(float2*)(out + row * (long)NDIM + col) = make_float2(q0, q1);
                }
            }
        }
    } else {
#pragma unroll
        for (int i = 0; i < 8; i++) {
            const long row = m0 + ty * 8 + i;
            float* orow = out + row * (long)NDIM + n0 + BNI + tx * 8;
#pragma unroll
            for (int jv = 0; jv < 2; jv++) {
                float4 v;
#pragma unroll
                for (int e = 0; e < 4; e++) {
                    const int j = jv * 4 + e;
                    const float b = bias[n0 + BNI + tx * 8 + j];
                    float y = __fmaf_rn((float)accd[i][j], sxw, b);
                    ((float*)&v)[e] = fminf(fmaxf(rintf(y), 0.0f), 255.0f);
                }
                *(float4*)(orow + jv * 4) = v;
            }
        }
    }
}

// --------------------------------------------------------------------- launch
extern "C" void kernel_launch(void* const* d_in, const int* in_sizes, int n_in,
                              void* d_out, int out_size) {
    (void)in_sizes; (void)n_in; (void)out_size;

    const int*   xq   = (const int*)d_in[0];
    const int*   wq   = (const int*)d_in[1];
    const float* bias = (const float*)d_in[2];

    const int nca = (MDIM * KDIM) / 16;   // 1,048,576
    const int ncb = (NDIM * KDIM) / 16;   // 2,818,048
    const int nct = nca + ncb;
    qk_cvt<<<(nct + 255) / 256, 256>>>(xq, wq, nca, ncb);

    cudaFuncSetAttribute(qk_gemm, cudaFuncAttributeMaxDynamicSharedMemorySize,
                         SMEM_TOTAL);
    dim3 grid(MDIM / BM, NGRP);           // (32, 43) m fastest
    qk_gemm<<<grid, 512, SMEM_TOTAL>>>((float*)d_out, bias);
}